// round 2
// baseline (speedup 1.0000x reference)
#include <cuda_runtime.h>
#include <cuda_bf16.h>

// Problem constants: B=16, C=128, KF=128, VF=128, H=128, W=128
#define NB 16
#define NC 128
#define NF 128
#define NH 128
#define NW 128

// ---------------------------------------------------------------------------
// Packed fp32x2 helpers (sm_103a FFMA2 via PTX fma.rn.f32x2)
// ---------------------------------------------------------------------------
typedef unsigned long long u64p;

__device__ __forceinline__ u64p pk_splat(float v) {
    u64p r; asm("mov.b64 %0, {%1, %1};" : "=l"(r) : "f"(v)); return r;
}
__device__ __forceinline__ u64p pk_pair(float lo, float hi) {
    u64p r; asm("mov.b64 %0, {%1, %2};" : "=l"(r) : "f"(lo), "f"(hi)); return r;
}
__device__ __forceinline__ void fma2(u64p& d, u64p a, u64p b) {
    asm("fma.rn.f32x2 %0, %1, %2, %0;" : "+l"(d) : "l"(a), "l"(b));
}
__device__ __forceinline__ float2 up2(u64p v) {
    float lo, hi; asm("mov.b64 {%0, %1}, %2;" : "=f"(lo), "=f"(hi) : "l"(v));
    return make_float2(lo, hi);
}

// ---------------------------------------------------------------------------
// Scratch (device globals: allocation-free per harness rules)
// ---------------------------------------------------------------------------
__device__ float g_Q[NB * NF * NH * NW];          // 134 MB  [b][f][h][w]
__device__ float g_K[NB * NF * NH * NW];          // 134 MB  [b][f][h][w]
__device__ float g_Spart[16 * NB * NH * NH];      // 16.8 MB [fg][b][h][g]
__device__ float g_Wt[NC * 256];                  // folded qk weights, [c][o]
__device__ float g_VwT[NC * NF];                  // transposed v weights, [c][vf]

// ---------------------------------------------------------------------------
// Kernel 0: fold + transpose weights
// ---------------------------------------------------------------------------
__global__ void prep_kernel(const float* __restrict__ qk_w,
                            const float* __restrict__ v_w) {
    int idx = blockIdx.x * blockDim.x + threadIdx.x;
    if (idx < NC * 256) {
        int c = idx >> 8;
        int o = idx & 255;
        g_Wt[idx] = qk_w[o * 256 + c] + qk_w[o * 256 + 128 + c];
    } else if (idx < NC * 256 + NC * NF) {
        int j = idx - NC * 256;
        int c = j >> 7;
        int vf = j & 127;
        g_VwT[j] = v_w[vf * NC + c];
    }
}

extern __shared__ float smem_dyn[];

// ---------------------------------------------------------------------------
// Kernel A: Q/K projection. CTA per (b, h). 256 threads, micro-tile 16(o)x8(w).
// FFMA2: pairs along o (contiguous in sW), splat x.
// ---------------------------------------------------------------------------
__global__ __launch_bounds__(256, 1)
void qk_kernel(const float* __restrict__ x, const float* __restrict__ qk_b) {
    float* sW = smem_dyn;              // [c][o] : c*256 + o
    float* sX = sW + NC * 256;         // [c][w] : c*128 + w
    float* sB = sX + NC * NW;          // [256]

    const int b = blockIdx.y;
    const int h = blockIdx.x;
    const int tid = threadIdx.x;

    #pragma unroll 4
    for (int i = 0; i < 128; i++) sW[tid + i * 256] = g_Wt[tid + i * 256];

    const float* xbase = x + (size_t)b * NC * NH * NW + (size_t)h * NW;
    #pragma unroll 4
    for (int i = 0; i < 64; i++) {
        int idx = tid + i * 256;
        sX[idx] = xbase[(idx >> 7) * (NH * NW) + (idx & 127)];
    }
    sB[tid] = qk_b[tid];
    __syncthreads();

    const int o0 = (tid >> 4) * 16;
    const int w0 = (tid & 15) * 8;

    u64p acc[8][8];   // [o-pair][w]
    #pragma unroll
    for (int i = 0; i < 8; i++)
        #pragma unroll
        for (int j = 0; j < 8; j++) acc[i][j] = 0ull;

    for (int c = 0; c < 128; c++) {
        u64p wv[8];
        {
            const ulonglong2* wp = (const ulonglong2*)(sW + c * 256 + o0);
            ulonglong2 t0 = wp[0], t1 = wp[1], t2 = wp[2], t3 = wp[3];
            wv[0] = t0.x; wv[1] = t0.y; wv[2] = t1.x; wv[3] = t1.y;
            wv[4] = t2.x; wv[5] = t2.y; wv[6] = t3.x; wv[7] = t3.y;
        }
        u64p xv[8];
        {
            float4 u0 = *(const float4*)(sX + c * 128 + w0);
            float4 u1 = *(const float4*)(sX + c * 128 + w0 + 4);
            xv[0] = pk_splat(u0.x); xv[1] = pk_splat(u0.y);
            xv[2] = pk_splat(u0.z); xv[3] = pk_splat(u0.w);
            xv[4] = pk_splat(u1.x); xv[5] = pk_splat(u1.y);
            xv[6] = pk_splat(u1.z); xv[7] = pk_splat(u1.w);
        }
        #pragma unroll
        for (int i = 0; i < 8; i++)
            #pragma unroll
            for (int j = 0; j < 8; j++)
                fma2(acc[i][j], wv[i], xv[j]);
    }

    // epilogue: add bias, write Q or K (pair rows olo/ohi)
    #pragma unroll
    for (int i = 0; i < 8; i++) {
        int olo = o0 + 2 * i;
        int ohi = olo + 1;
        float blo = sB[olo], bhi = sB[ohi];
        float rlo[8], rhi[8];
        #pragma unroll
        for (int j = 0; j < 8; j++) {
            float2 p = up2(acc[i][j]);
            rlo[j] = p.x + blo;
            rhi[j] = p.y + bhi;
        }
        float* dlo;
        float* dhi;
        if (olo < 128) {
            dlo = &g_Q[(((size_t)b * NF + olo) * NH + h) * NW + w0];
            dhi = &g_Q[(((size_t)b * NF + ohi) * NH + h) * NW + w0];
        } else {
            dlo = &g_K[(((size_t)b * NF + (olo - 128)) * NH + h) * NW + w0];
            dhi = &g_K[(((size_t)b * NF + (ohi - 128)) * NH + h) * NW + w0];
        }
        *(float4*)dlo = make_float4(rlo[0], rlo[1], rlo[2], rlo[3]);
        *(float4*)(dlo + 4) = make_float4(rlo[4], rlo[5], rlo[6], rlo[7]);
        *(float4*)dhi = make_float4(rhi[0], rhi[1], rhi[2], rhi[3]);
        *(float4*)(dhi + 4) = make_float4(rhi[4], rhi[5], rhi[6], rhi[7]);
    }
}

// ---------------------------------------------------------------------------
// Kernel B: scores + causal exp-softmax + sum over f (8 f's per CTA).
// CTA per (fg, b). 256 threads, micro-tile 8(h)x8(g), FFMA2 pairs along h.
// Deterministic: tree row-sum, plain stores (no atomics).
// ---------------------------------------------------------------------------
__global__ __launch_bounds__(256, 1)
void attn_kernel() {
    float* qT = smem_dyn;                  // [w][h] : w*132 + h
    float* kT = qT + 128 * 132;            // [w][g] : w*132 + g
    float* red = kT + 128 * 132;           // [h][t] : h*16 + t

    const int fg = blockIdx.x;
    const int b = blockIdx.y;
    const int tid = threadIdx.x;
    const int tg = tid & 15;
    const int h0 = (tid >> 4) * 8;
    const int g0 = tg * 8;
    const float scale = 0.088388347648318447f;  // 128^-0.5

    u64p Sacc[4][8];   // packed pairs along h
    #pragma unroll
    for (int i = 0; i < 4; i++)
        #pragma unroll
        for (int j = 0; j < 8; j++) Sacc[i][j] = 0ull;

    for (int fi = 0; fi < 8; fi++) {
        const int f = fg * 8 + fi;
        const float* qsrc = &g_Q[((size_t)b * NF + f) * NH * NW];
        const float* ksrc = &g_K[((size_t)b * NF + f) * NH * NW];

        // transpose-load into smem: qT[w][h] = q[h][w]
        #pragma unroll 4
        for (int i = 0; i < 64; i++) {
            int idx = tid + i * 256;
            int hh = idx >> 7;
            int w = idx & 127;
            qT[w * 132 + hh] = qsrc[idx];
            kT[w * 132 + hh] = ksrc[idx];
        }
        __syncthreads();

        u64p acc[4][8];
        #pragma unroll
        for (int i = 0; i < 4; i++)
            #pragma unroll
            for (int j = 0; j < 8; j++) acc[i][j] = 0ull;

        for (int w = 0; w < 128; w++) {
            u64p av[4];
            {
                const ulonglong2* qp = (const ulonglong2*)(qT + w * 132 + h0);
                ulonglong2 a0 = qp[0], a1 = qp[1];
                av[0] = a0.x; av[1] = a0.y; av[2] = a1.x; av[3] = a1.y;
            }
            u64p bv[8];
            {
                float4 u0 = *(const float4*)(kT + w * 132 + g0);
                float4 u1 = *(const float4*)(kT + w * 132 + g0 + 4);
                bv[0] = pk_splat(u0.x); bv[1] = pk_splat(u0.y);
                bv[2] = pk_splat(u0.z); bv[3] = pk_splat(u0.w);
                bv[4] = pk_splat(u1.x); bv[5] = pk_splat(u1.y);
                bv[6] = pk_splat(u1.z); bv[7] = pk_splat(u1.w);
            }
            #pragma unroll
            for (int i = 0; i < 4; i++)
                #pragma unroll
                for (int j = 0; j < 8; j++)
                    fma2(acc[i][j], av[i], bv[j]);
        }

        // masked exp + per-thread partial row sums (repacked in place)
        float ps[8];
        #pragma unroll
        for (int i = 0; i < 8; i++) ps[i] = 0.0f;
        #pragma unroll
        for (int i2 = 0; i2 < 4; i2++) {
            int hlo = h0 + 2 * i2;
            int hhi = hlo + 1;
            #pragma unroll
            for (int j = 0; j < 8; j++) {
                int gg = g0 + j;
                float2 p = up2(acc[i2][j]);
                float elo = (gg <= hlo) ? __expf(p.x * scale) : 0.0f;
                float ehi = (gg <= hhi) ? __expf(p.y * scale) : 0.0f;
                acc[i2][j] = pk_pair(elo, ehi);
                ps[2 * i2] += elo;
                ps[2 * i2 + 1] += ehi;
            }
        }
        #pragma unroll
        for (int i = 0; i < 8; i++) red[(h0 + i) * 16 + tg] = ps[i];
        __syncthreads();

        #pragma unroll
        for (int i2 = 0; i2 < 4; i2++) {
            float rslo = 0.0f, rshi = 0.0f;
            #pragma unroll
            for (int t = 0; t < 16; t++) {
                rslo += red[(h0 + 2 * i2) * 16 + t];
                rshi += red[(h0 + 2 * i2 + 1) * 16 + t];
            }
            u64p inv2 = pk_pair(1.0f / rslo, 1.0f / rshi);  // diagonal in-mask -> >0
            #pragma unroll
            for (int j = 0; j < 8; j++)
                fma2(Sacc[i2][j], acc[i2][j], inv2);
        }
        __syncthreads();  // before smem tiles are overwritten next f
    }

    // plain (deterministic) partial store
    float* dst = &g_Spart[((size_t)fg * NB + b) * NH * NH];
    #pragma unroll
    for (int i2 = 0; i2 < 4; i2++) {
        float rlo[8], rhi[8];
        #pragma unroll
        for (int j = 0; j < 8; j++) {
            float2 p = up2(Sacc[i2][j]);
            rlo[j] = p.x;
            rhi[j] = p.y;
        }
        float* plo = dst + (h0 + 2 * i2) * NH + g0;
        float* phi = dst + (h0 + 2 * i2 + 1) * NH + g0;
        *(float4*)plo = make_float4(rlo[0], rlo[1], rlo[2], rlo[3]);
        *(float4*)(plo + 4) = make_float4(rlo[4], rlo[5], rlo[6], rlo[7]);
        *(float4*)phi = make_float4(rhi[0], rhi[1], rhi[2], rhi[3]);
        *(float4*)(phi + 4) = make_float4(rhi[4], rhi[5], rhi[6], rhi[7]);
    }
}

// ---------------------------------------------------------------------------
// Kernel C: V projection fused with S-scale epilogue. CTA per (b, h).
// 256 threads, micro-tile 8(vf)x8(w), FFMA2 pairs along vf.
// ---------------------------------------------------------------------------
__global__ __launch_bounds__(256, 1)
void out_kernel(const float* __restrict__ x, const float* __restrict__ v_b,
                float* __restrict__ out) {
    float* sV = smem_dyn;              // [c][vf]
    float* sX = sV + NC * NF;          // [c][w]
    float* sS = sX + NC * NW;          // [128]
    float* sB = sS + 128;              // [128]

    const int b = blockIdx.y;
    const int h = blockIdx.x;
    const int tid = threadIdx.x;

    #pragma unroll 4
    for (int i = 0; i < 64; i++) sV[tid + i * 256] = g_VwT[tid + i * 256];
    const float* xbase = x + (size_t)b * NC * NH * NW + (size_t)h * NW;
    #pragma unroll 4
    for (int i = 0; i < 64; i++) {
        int idx = tid + i * 256;
        sX[idx] = xbase[(idx >> 7) * (NH * NW) + (idx & 127)];
    }
    if (tid < 128) {
        float s = 0.0f;
        #pragma unroll
        for (int fg = 0; fg < 16; fg++)
            s += g_Spart[(((size_t)fg * NB + b) * NH + h) * NH + tid];
        sS[tid] = s;
        sB[tid] = v_b[tid];
    }
    __syncthreads();

    const int v0 = (tid >> 4) * 8;
    const int w0 = (tid & 15) * 8;

    u64p acc[4][8];   // pairs along vf
    #pragma unroll
    for (int i = 0; i < 4; i++)
        #pragma unroll
        for (int j = 0; j < 8; j++) acc[i][j] = 0ull;

    for (int c = 0; c < 128; c++) {
        u64p vv[4];
        {
            const ulonglong2* vp = (const ulonglong2*)(sV + c * 128 + v0);
            ulonglong2 t0 = vp[0], t1 = vp[1];
            vv[0] = t0.x; vv[1] = t0.y; vv[2] = t1.x; vv[3] = t1.y;
        }
        u64p xv[8];
        {
            float4 u0 = *(const float4*)(sX + c * 128 + w0);
            float4 u1 = *(const float4*)(sX + c * 128 + w0 + 4);
            xv[0] = pk_splat(u0.x); xv[1] = pk_splat(u0.y);
            xv[2] = pk_splat(u0.z); xv[3] = pk_splat(u0.w);
            xv[4] = pk_splat(u1.x); xv[5] = pk_splat(u1.y);
            xv[6] = pk_splat(u1.z); xv[7] = pk_splat(u1.w);
        }
        #pragma unroll
        for (int i = 0; i < 4; i++)
            #pragma unroll
            for (int j = 0; j < 8; j++)
                fma2(acc[i][j], vv[i], xv[j]);
    }

    float sreg[8];
    #pragma unroll
    for (int j = 0; j < 8; j++) sreg[j] = sS[w0 + j];

    #pragma unroll
    for (int i2 = 0; i2 < 4; i2++) {
        int vlo = v0 + 2 * i2;
        int vhi = vlo + 1;
        float blo = sB[vlo], bhi = sB[vhi];
        float rlo[8], rhi[8];
        #pragma unroll
        for (int j = 0; j < 8; j++) {
            float2 p = up2(acc[i2][j]);
            rlo[j] = (p.x + blo) * sreg[j];
            rhi[j] = (p.y + bhi) * sreg[j];
        }
        float* dlo = out + (((size_t)b * NF + vlo) * NH + h) * NW + w0;
        float* dhi = out + (((size_t)b * NF + vhi) * NH + h) * NW + w0;
        *(float4*)dlo = make_float4(rlo[0], rlo[1], rlo[2], rlo[3]);
        *(float4*)(dlo + 4) = make_float4(rlo[4], rlo[5], rlo[6], rlo[7]);
        *(float4*)dhi = make_float4(rhi[0], rhi[1], rhi[2], rhi[3]);
        *(float4*)(dhi + 4) = make_float4(rhi[4], rhi[5], rhi[6], rhi[7]);
    }
}

// ---------------------------------------------------------------------------
// Launch
// ---------------------------------------------------------------------------
extern "C" void kernel_launch(void* const* d_in, const int* in_sizes, int n_in,
                              void* d_out, int out_size) {
    const float* x    = (const float*)d_in[0];
    const float* qk_w = (const float*)d_in[1];
    const float* qk_b = (const float*)d_in[2];
    const float* v_w  = (const float*)d_in[3];
    const float* v_b  = (const float*)d_in[4];
    float* out = (float*)d_out;

    const int SMEM_A = (NC * 256 + NC * NW + 256) * 4;          // 197632
    const int SMEM_B = (128 * 132 * 2 + 128 * 16) * 4;          // 143360
    const int SMEM_C = (NC * NF + NC * NW + 128 + 128) * 4;     // 132096

    cudaFuncSetAttribute(qk_kernel,   cudaFuncAttributeMaxDynamicSharedMemorySize, SMEM_A);
    cudaFuncSetAttribute(attn_kernel, cudaFuncAttributeMaxDynamicSharedMemorySize, SMEM_B);
    cudaFuncSetAttribute(out_kernel,  cudaFuncAttributeMaxDynamicSharedMemorySize, SMEM_C);

    prep_kernel<<<192, 256>>>(qk_w, v_w);
    qk_kernel<<<dim3(NH, NB), 256, SMEM_A>>>(x, qk_b);
    attn_kernel<<<dim3(16, NB), 256, SMEM_B>>>();
    out_kernel<<<dim3(NH, NB), 256, SMEM_C>>>(x, v_b, out);
}

// round 6
// speedup vs baseline: 1.1779x; 1.1779x over previous
#include <cuda_runtime.h>
#include <cuda_bf16.h>

// Problem constants: B=16, C=128, KF=128, VF=128, H=128, W=128
#define NB 16
#define NC 128
#define NF 128
#define NH 128
#define NW 128
#define NFG 64           // f-groups in attn kernel (2 f's per group)

// ---------------------------------------------------------------------------
// Packed fp32x2 helpers (sm_103a FFMA2 via PTX fma.rn.f32x2)
// ---------------------------------------------------------------------------
typedef unsigned long long u64p;

__device__ __forceinline__ u64p pk_splat(float v) {
    u64p r; asm("mov.b64 %0, {%1, %1};" : "=l"(r) : "f"(v)); return r;
}
__device__ __forceinline__ u64p pk_pair(float lo, float hi) {
    u64p r; asm("mov.b64 %0, {%1, %2};" : "=l"(r) : "f"(lo), "f"(hi)); return r;
}
__device__ __forceinline__ void fma2(u64p& d, u64p a, u64p b) {
    asm("fma.rn.f32x2 %0, %1, %2, %0;" : "+l"(d) : "l"(a), "l"(b));
}
__device__ __forceinline__ float2 up2(u64p v) {
    float lo, hi; asm("mov.b64 {%0, %1}, %2;" : "=f"(lo), "=f"(hi) : "l"(v));
    return make_float2(lo, hi);
}

// ---------------------------------------------------------------------------
// Scratch (device globals: allocation-free per harness rules)
// ---------------------------------------------------------------------------
__device__ float g_Q[NB * NF * NH * NW];            // 134 MB  [b][f][h][w]
__device__ float g_K[NB * NF * NH * NW];            // 134 MB  [b][f][h][w]
__device__ float g_Spart[NFG * NB * NH * NH];       // 67 MB   [fg][b][h][g]
__device__ float g_Wt[NC * 256];                    // folded qk weights, [c][o]
__device__ float g_VwT[NC * NF];                    // transposed v weights, [c][vf]

// ---------------------------------------------------------------------------
// Kernel 0: fold + transpose weights
// ---------------------------------------------------------------------------
__global__ void prep_kernel(const float* __restrict__ qk_w,
                            const float* __restrict__ v_w) {
    int idx = blockIdx.x * blockDim.x + threadIdx.x;
    if (idx < NC * 256) {
        int c = idx >> 8;
        int o = idx & 255;
        g_Wt[idx] = qk_w[o * 256 + c] + qk_w[o * 256 + 128 + c];
    } else if (idx < NC * 256 + NC * NF) {
        int j = idx - NC * 256;
        int c = j >> 7;
        int vf = j & 127;
        g_VwT[j] = v_w[vf * NC + c];
    }
}

extern __shared__ float smem_dyn[];

// ---------------------------------------------------------------------------
// Kernel A: Q/K projection. CTA per (b, h). 512 threads, micro-tile 8(o)x8(w).
// 16 warps/SM (4/SMSP) to hide LDS latency; FFMA2 pairs along o.
// ---------------------------------------------------------------------------
__global__ __launch_bounds__(512, 1)
void qk_kernel(const float* __restrict__ x, const float* __restrict__ qk_b) {
    float* sW = smem_dyn;              // [c][o] : c*256 + o
    float* sX = sW + NC * 256;         // [c][w] : c*128 + w
    float* sB = sX + NC * NW;          // [256]

    const int b = blockIdx.y;
    const int h = blockIdx.x;
    const int tid = threadIdx.x;

    #pragma unroll 4
    for (int i = 0; i < 64; i++) sW[tid + i * 512] = g_Wt[tid + i * 512];

    const float* xbase = x + (size_t)b * NC * NH * NW + (size_t)h * NW;
    #pragma unroll 4
    for (int i = 0; i < 32; i++) {
        int idx = tid + i * 512;
        sX[idx] = xbase[(idx >> 7) * (NH * NW) + (idx & 127)];
    }
    if (tid < 256) sB[tid] = qk_b[tid];
    __syncthreads();

    const int o0 = (tid >> 4) * 8;     // 32 o-threads
    const int w0 = (tid & 15) * 8;     // 16 w-threads

    u64p acc[4][8];   // [o-pair][w]
    #pragma unroll
    for (int i = 0; i < 4; i++)
        #pragma unroll
        for (int j = 0; j < 8; j++) acc[i][j] = 0ull;

    for (int c = 0; c < 128; c++) {
        u64p wv[4];
        {
            const ulonglong2* wp = (const ulonglong2*)(sW + c * 256 + o0);
            ulonglong2 t0 = wp[0], t1 = wp[1];
            wv[0] = t0.x; wv[1] = t0.y; wv[2] = t1.x; wv[3] = t1.y;
        }
        u64p xv[8];
        {
            float4 u0 = *(const float4*)(sX + c * 128 + w0);
            float4 u1 = *(const float4*)(sX + c * 128 + w0 + 4);
            xv[0] = pk_splat(u0.x); xv[1] = pk_splat(u0.y);
            xv[2] = pk_splat(u0.z); xv[3] = pk_splat(u0.w);
            xv[4] = pk_splat(u1.x); xv[5] = pk_splat(u1.y);
            xv[6] = pk_splat(u1.z); xv[7] = pk_splat(u1.w);
        }
        #pragma unroll
        for (int i = 0; i < 4; i++)
            #pragma unroll
            for (int j = 0; j < 8; j++)
                fma2(acc[i][j], wv[i], xv[j]);
    }

    // epilogue: add bias, write Q or K (pair rows olo/ohi)
    #pragma unroll
    for (int i = 0; i < 4; i++) {
        int olo = o0 + 2 * i;
        int ohi = olo + 1;
        float blo = sB[olo], bhi = sB[ohi];
        float rlo[8], rhi[8];
        #pragma unroll
        for (int j = 0; j < 8; j++) {
            float2 p = up2(acc[i][j]);
            rlo[j] = p.x + blo;
            rhi[j] = p.y + bhi;
        }
        float* dlo;
        float* dhi;
        if (olo < 128) {
            dlo = &g_Q[(((size_t)b * NF + olo) * NH + h) * NW + w0];
            dhi = &g_Q[(((size_t)b * NF + ohi) * NH + h) * NW + w0];
        } else {
            dlo = &g_K[(((size_t)b * NF + (olo - 128)) * NH + h) * NW + w0];
            dhi = &g_K[(((size_t)b * NF + (ohi - 128)) * NH + h) * NW + w0];
        }
        *(float4*)dlo = make_float4(rlo[0], rlo[1], rlo[2], rlo[3]);
        *(float4*)(dlo + 4) = make_float4(rlo[4], rlo[5], rlo[6], rlo[7]);
        *(float4*)dhi = make_float4(rhi[0], rhi[1], rhi[2], rhi[3]);
        *(float4*)(dhi + 4) = make_float4(rhi[4], rhi[5], rhi[6], rhi[7]);
    }
}

// ---------------------------------------------------------------------------
// Kernel B: scores + causal exp-softmax + sum over f (2 f's per CTA).
// CTA per (fg, b): fg in [0,64). 512 threads.
// Triangular warp tiling: 16 warps cover a 4x4 grid of 32x32 (h,g) tiles.
// SMSP-balanced permuted map: active (tj<=ti) tiles on wids 0..9 so each
// SMSP (wid%4) gets 3,3,2,2 active warps (unpermuted map gave 4,3,2,1 and a
// single-warp latency-bound SMSP). Masked warps keep their zero-fill duties.
// Micro-tile 4(h) x 8(g) per lane, FFMA2 pairs along h.
// Deterministic: fixed 16-slot-per-row tree sum, plain stores.
// ---------------------------------------------------------------------------
#define TI_PACK 0x2110003333222110ull
#define TJ_PACK 0x3323213210210100ull

__global__ __launch_bounds__(512, 1)
void attn_kernel() {
    float* qT = smem_dyn;                  // [w][h] : w*132 + h
    float* kT = qT + 128 * 132;            // [w][g] : w*132 + g
    float* red = kT + 128 * 132;           // [h][t] : h*16 + t

    const int fg = blockIdx.x;
    const int b = blockIdx.y;
    const int tid = threadIdx.x;
    const int wid = tid >> 5;
    const int lane = tid & 31;
    const int ti = (int)((TI_PACK >> (wid * 4)) & 15ull);  // h-tile 0..3
    const int tj = (int)((TJ_PACK >> (wid * 4)) & 15ull);  // g-tile 0..3
    const bool active = (tj <= ti);        // below/at diagonal (wids 0..9)
    const int h0 = ti * 32 + (lane >> 2) * 4;   // 4 h rows
    const int g0 = tj * 32 + (lane & 3) * 8;    // 8 g cols
    const int rcol = tj * 4 + (lane & 3);       // unique red column per row
    const float scale = 0.088388347648318447f;  // 128^-0.5

    u64p Sacc[2][8];   // packed pairs along h
    #pragma unroll
    for (int i = 0; i < 2; i++)
        #pragma unroll
        for (int j = 0; j < 8; j++) Sacc[i][j] = 0ull;

    for (int fi = 0; fi < 2; fi++) {
        const int f = fg * 2 + fi;
        const float* qsrc = &g_Q[((size_t)b * NF + f) * NH * NW];
        const float* ksrc = &g_K[((size_t)b * NF + f) * NH * NW];

        // transpose-load into smem: qT[w][h] = q[h][w] (all threads help)
        #pragma unroll 4
        for (int i = 0; i < 32; i++) {
            int idx = tid + i * 512;
            int hh = idx >> 7;
            int w = idx & 127;
            qT[w * 132 + hh] = qsrc[idx];
            kT[w * 132 + hh] = ksrc[idx];
        }
        __syncthreads();

        float ps[4];
        #pragma unroll
        for (int i = 0; i < 4; i++) ps[i] = 0.0f;

        u64p acc[2][8];
        #pragma unroll
        for (int i = 0; i < 2; i++)
            #pragma unroll
            for (int j = 0; j < 8; j++) acc[i][j] = 0ull;

        if (active) {
            for (int w = 0; w < 128; w++) {
                u64p av[2];
                {
                    ulonglong2 a0 = *(const ulonglong2*)(qT + w * 132 + h0);
                    av[0] = a0.x; av[1] = a0.y;
                }
                u64p bv[8];
                {
                    float4 u0 = *(const float4*)(kT + w * 132 + g0);
                    float4 u1 = *(const float4*)(kT + w * 132 + g0 + 4);
                    bv[0] = pk_splat(u0.x); bv[1] = pk_splat(u0.y);
                    bv[2] = pk_splat(u0.z); bv[3] = pk_splat(u0.w);
                    bv[4] = pk_splat(u1.x); bv[5] = pk_splat(u1.y);
                    bv[6] = pk_splat(u1.z); bv[7] = pk_splat(u1.w);
                }
                #pragma unroll
                for (int i = 0; i < 2; i++)
                    #pragma unroll
                    for (int j = 0; j < 8; j++)
                        fma2(acc[i][j], av[i], bv[j]);
            }

            // masked exp + per-thread partial row sums (repacked in place)
            #pragma unroll
            for (int i2 = 0; i2 < 2; i2++) {
                int hlo = h0 + 2 * i2;
                int hhi = hlo + 1;
                #pragma unroll
                for (int j = 0; j < 8; j++) {
                    int gg = g0 + j;
                    float2 p = up2(acc[i2][j]);
                    float elo = (gg <= hlo) ? __expf(p.x * scale) : 0.0f;
                    float ehi = (gg <= hhi) ? __expf(p.y * scale) : 0.0f;
                    acc[i2][j] = pk_pair(elo, ehi);
                    ps[2 * i2] += elo;
                    ps[2 * i2 + 1] += ehi;
                }
            }
        }

        // every warp (incl. masked) fills its 16-slot columns -> no stale data
        #pragma unroll
        for (int i = 0; i < 4; i++) red[(h0 + i) * 16 + rcol] = ps[i];
        __syncthreads();

        if (active) {
            #pragma unroll
            for (int i2 = 0; i2 < 2; i2++) {
                float rslo = 0.0f, rshi = 0.0f;
                #pragma unroll
                for (int t = 0; t < 16; t++) {
                    rslo += red[(h0 + 2 * i2) * 16 + t];
                    rshi += red[(h0 + 2 * i2 + 1) * 16 + t];
                }
                u64p inv2 = pk_pair(1.0f / rslo, 1.0f / rshi);  // diag in-mask -> >0
                #pragma unroll
                for (int j = 0; j < 8; j++)
                    fma2(Sacc[i2][j], acc[i2][j], inv2);
            }
        }
        __syncthreads();  // before smem tiles are overwritten next f
    }

    // plain (deterministic) store; masked warps store exact zeros
    float* dst = &g_Spart[((size_t)fg * NB + b) * NH * NH];
    #pragma unroll
    for (int i2 = 0; i2 < 2; i2++) {
        float rlo[8], rhi[8];
        #pragma unroll
        for (int j = 0; j < 8; j++) {
            float2 p = up2(Sacc[i2][j]);
            rlo[j] = p.x;
            rhi[j] = p.y;
        }
        float* plo = dst + (h0 + 2 * i2) * NH + g0;
        float* phi = dst + (h0 + 2 * i2 + 1) * NH + g0;
        *(float4*)plo = make_float4(rlo[0], rlo[1], rlo[2], rlo[3]);
        *(float4*)(plo + 4) = make_float4(rlo[4], rlo[5], rlo[6], rlo[7]);
        *(float4*)phi = make_float4(rhi[0], rhi[1], rhi[2], rhi[3]);
        *(float4*)(phi + 4) = make_float4(rhi[4], rhi[5], rhi[6], rhi[7]);
    }
}

// ---------------------------------------------------------------------------
// Kernel C: V projection fused with S-scale epilogue. CTA per (b, h).
// 512 threads, micro-tile 4(vf)x8(w), FFMA2 pairs along vf.
// S reduced from 64 f-group partials (fixed order -> deterministic).
// ---------------------------------------------------------------------------
__global__ __launch_bounds__(512, 1)
void out_kernel(const float* __restrict__ x, const float* __restrict__ v_b,
                float* __restrict__ out) {
    float* sV = smem_dyn;              // [c][vf]
    float* sX = sV + NC * NF;          // [c][w]
    float* sSp = sX + NC * NW;         // [4][128] partial S sums
    float* sS = sSp + 4 * 128;         // [128]
    float* sB = sS + 128;              // [128]

    const int b = blockIdx.y;
    const int h = blockIdx.x;
    const int tid = threadIdx.x;

    #pragma unroll 4
    for (int i = 0; i < 32; i++) sV[tid + i * 512] = g_VwT[tid + i * 512];
    const float* xbase = x + (size_t)b * NC * NH * NW + (size_t)h * NW;
    #pragma unroll 4
    for (int i = 0; i < 32; i++) {
        int idx = tid + i * 512;
        sX[idx] = xbase[(idx >> 7) * (NH * NW) + (idx & 127)];
    }
    // parallel partial reduction of the 64 S partials (deterministic order)
    {
        int part = tid >> 7;           // 0..3
        int w = tid & 127;
        float s = 0.0f;
        #pragma unroll
        for (int k = 0; k < 16; k++) {
            int fg = part * 16 + k;
            s += g_Spart[(((size_t)fg * NB + b) * NH + h) * NH + w];
        }
        sSp[part * 128 + w] = s;
    }
    if (tid < 128) sB[tid] = v_b[tid];
    __syncthreads();
    if (tid < 128)
        sS[tid] = ((sSp[tid] + sSp[128 + tid]) + sSp[256 + tid]) + sSp[384 + tid];
    __syncthreads();

    const int v0 = (tid >> 4) * 4;     // 32 vf-threads
    const int w0 = (tid & 15) * 8;     // 16 w-threads

    u64p acc[2][8];   // pairs along vf
    #pragma unroll
    for (int i = 0; i < 2; i++)
        #pragma unroll
        for (int j = 0; j < 8; j++) acc[i][j] = 0ull;

    for (int c = 0; c < 128; c++) {
        u64p vv[2];
        {
            ulonglong2 t0 = *(const ulonglong2*)(sV + c * 128 + v0);
            vv[0] = t0.x; vv[1] = t0.y;
        }
        u64p xv[8];
        {
            float4 u0 = *(const float4*)(sX + c * 128 + w0);
            float4 u1 = *(const float4*)(sX + c * 128 + w0 + 4);
            xv[0] = pk_splat(u0.x); xv[1] = pk_splat(u0.y);
            xv[2] = pk_splat(u0.z); xv[3] = pk_splat(u0.w);
            xv[4] = pk_splat(u1.x); xv[5] = pk_splat(u1.y);
            xv[6] = pk_splat(u1.z); xv[7] = pk_splat(u1.w);
        }
        #pragma unroll
        for (int i = 0; i < 2; i++)
            #pragma unroll
            for (int j = 0; j < 8; j++)
                fma2(acc[i][j], vv[i], xv[j]);
    }

    float sreg[8];
    #pragma unroll
    for (int j = 0; j < 8; j++) sreg[j] = sS[w0 + j];

    #pragma unroll
    for (int i2 = 0; i2 < 2; i2++) {
        int vlo = v0 + 2 * i2;
        int vhi = vlo + 1;
        float blo = sB[vlo], bhi = sB[vhi];
        float rlo[8], rhi[8];
        #pragma unroll
        for (int j = 0; j < 8; j++) {
            float2 p = up2(acc[i2][j]);
            rlo[j] = (p.x + blo) * sreg[j];
            rhi[j] = (p.y + bhi) * sreg[j];
        }
        float* dlo = out + (((size_t)b * NF + vlo) * NH + h) * NW + w0;
        float* dhi = out + (((size_t)b * NF + vhi) * NH + h) * NW + w0;
        *(float4*)dlo = make_float4(rlo[0], rlo[1], rlo[2], rlo[3]);
        *(float4*)(dlo + 4) = make_float4(rlo[4], rlo[5], rlo[6], rlo[7]);
        *(float4*)dhi = make_float4(rhi[0], rhi[1], rhi[2], rhi[3]);
        *(float4*)(dhi + 4) = make_float4(rhi[4], rhi[5], rhi[6], rhi[7]);
    }
}

// ---------------------------------------------------------------------------
// Launch
// ---------------------------------------------------------------------------
extern "C" void kernel_launch(void* const* d_in, const int* in_sizes, int n_in,
                              void* d_out, int out_size) {
    const float* x    = (const float*)d_in[0];
    const float* qk_w = (const float*)d_in[1];
    const float* qk_b = (const float*)d_in[2];
    const float* v_w  = (const float*)d_in[3];
    const float* v_b  = (const float*)d_in[4];
    float* out = (float*)d_out;

    const int SMEM_A = (NC * 256 + NC * NW + 256) * 4;                 // 197632
    const int SMEM_B = (128 * 132 * 2 + 128 * 16) * 4;                 // 143360
    const int SMEM_C = (NC * NF + NC * NW + 4 * 128 + 128 + 128) * 4;  // 134144

    cudaFuncSetAttribute(qk_kernel,   cudaFuncAttributeMaxDynamicSharedMemorySize, SMEM_A);
    cudaFuncSetAttribute(attn_kernel, cudaFuncAttributeMaxDynamicSharedMemorySize, SMEM_B);
    cudaFuncSetAttribute(out_kernel,  cudaFuncAttributeMaxDynamicSharedMemorySize, SMEM_C);

    prep_kernel<<<192, 256>>>(qk_w, v_w);
    qk_kernel<<<dim3(NH, NB), 512, SMEM_A>>>(x, qk_b);
    attn_kernel<<<dim3(NFG, NB), 512, SMEM_B>>>();
    out_kernel<<<dim3(NH, NB), 512, SMEM_C>>>(x, v_b, out);
}